// round 2
// baseline (speedup 1.0000x reference)
#include <cuda_runtime.h>

// WindowAttention fused kernel, fp32 via packed fma.rn.f32x2 (sm_103a).
// One CTA per batch element b (4096 CTAs x 256 threads), ~165KB dynamic smem.

#define NB    4096
#define NT    64
#define CD    128
#define NHD   4
#define HDM   32
#define NWN   2048
#define SCALE_F 0.17677669529663687f   // 32^-0.5

#define LDN 66     // padded leading dim for k-major [*][64] arrays (floats)
#define LDV 132    // v row-major [64][128] padded (16B-aligned rows)
#define LDW 260    // staged weight chunk [16][256] padded (16B-aligned rows)
#define LDP 132    // p_t [128][128] padded (16B-aligned rows)

#define OFF_QT 0                       // q_t [128][LDN]  (aliased by o_t after G2)
#define OFF_KT (128*LDN)               // k_t [128][LDN]
#define OFF_V  (2*128*LDN)             // v   [64][LDV]
#define OFF_AT (OFF_V + 64*LDV)        // y_t [128][LDN] -> attn_t [256][LDN] -> p_t [128][LDP]
#define OFF_W  (OFF_AT + 128*LDN)      // w chunk [16][LDW] (lives in upper half of attn region)
#define SMEM_FLOATS (OFF_AT + 256*LDN) // 42240 floats
#define SMEM_BYTES  (SMEM_FLOATS * 4)  // 168960 B

typedef unsigned long long u64;

__device__ __forceinline__ u64 pk2(float v) {
    u64 r;
    asm("mov.b64 %0, {%1, %1};" : "=l"(r) : "f"(v));
    return r;
}
__device__ __forceinline__ u64 f2fma(u64 a, u64 b, u64 c) {
    u64 d;
    asm("fma.rn.f32x2 %0, %1, %2, %3;" : "=l"(d) : "l"(a), "l"(b), "l"(c));
    return d;
}
__device__ __forceinline__ u64 f2add(u64 a, u64 b) {
    u64 d;
    asm("add.rn.f32x2 %0, %1, %2;" : "=l"(d) : "l"(a), "l"(b));
    return d;
}
__device__ __forceinline__ void upk2(u64 v, float& lo, float& hi) {
    asm("mov.b64 {%0, %1}, %2;" : "=f"(lo), "=f"(hi) : "l"(v));
}
__device__ __forceinline__ u64 lds2(const float* p) {
    return *reinterpret_cast<const u64*>(p);
}

__global__ void __launch_bounds__(256, 1)
wattn_kernel(const float* __restrict__ x, const float* __restrict__ y,
             const float* __restrict__ P, const float* __restrict__ maskp,
             const float* __restrict__ qkv_w, const float* __restrict__ qkv_b,
             const float* __restrict__ proj_w, const float* __restrict__ proj_b,
             const float* __restrict__ lam_p, float* __restrict__ out)
{
    extern __shared__ float sm[];
    const int b   = blockIdx.x;
    const int tid = threadIdx.x;

    // ============ Phase 0: x -> q_t (k-major, scaled), y -> y_t (k-major) ============
    // q[b,h,n,d] = x[b] flat[h*2048 + n*32 + d]  (axis-mixing reshape).
    {
        const float4* xb = (const float4*)(x + (size_t)b * 8192);
        const float4* yb = (const float4*)(y + (size_t)b * 8192);
        #pragma unroll
        for (int it = 0; it < 8; ++it) {
            int idx = tid + it * 256;
            int i   = idx << 2;
            float4 xv = xb[idx];
            int h = i >> 11, r = i & 2047, n = r >> 5, d = r & 31;
            int qb = OFF_QT + ((h << 5) + d) * LDN + n;
            sm[qb        ] = xv.x * SCALE_F;
            sm[qb +   LDN] = xv.y * SCALE_F;
            sm[qb + 2*LDN] = xv.z * SCALE_F;
            sm[qb + 3*LDN] = xv.w * SCALE_F;
            float4 yv = yb[idx];
            int n2 = i >> 7, k = i & 127;
            int yo = OFF_AT + k * LDN + n2;
            sm[yo        ] = yv.x;
            sm[yo +   LDN] = yv.y;
            sm[yo + 2*LDN] = yv.z;
            sm[yo + 3*LDN] = yv.w;
        }
    }
    __syncthreads();

    // ============ GEMM1: kv[n][c] = sum_k y[n][k]*qkv_w[c][k] + qkv_b[c] ============
    // 64 x 256, K=128. Thread tile 8 rows (4 f32x2 pairs) x 8 cols.
    // k<128 -> k_t[c][n] (transposed), c>=128 -> v[n][c-128] (row-major).
    {
        const int tc = tid >> 3, tr = tid & 7;
        const int c0 = tc << 3, r0 = tr << 3;
        u64 acc[4][8];
        #pragma unroll
        for (int p = 0; p < 4; ++p)
            #pragma unroll
            for (int cc = 0; cc < 8; ++cc) acc[p][cc] = 0ull;

        for (int kk0 = 0; kk0 < 128; kk0 += 16) {
            // stage qkv_w[:, kk0:kk0+16] transposed into smem: w_t[j][c]
            float4 w0, w1, w2, w3;
            {
                const float4* wr = (const float4*)(qkv_w + tid * 128 + kk0);
                w0 = wr[0]; w1 = wr[1]; w2 = wr[2]; w3 = wr[3];
            }
            __syncthreads();   // previous chunk fully consumed
            {
                float wv[16] = {w0.x,w0.y,w0.z,w0.w, w1.x,w1.y,w1.z,w1.w,
                                w2.x,w2.y,w2.z,w2.w, w3.x,w3.y,w3.z,w3.w};
                #pragma unroll
                for (int j = 0; j < 16; ++j)
                    sm[OFF_W + j * LDW + tid] = wv[j];
            }
            __syncthreads();
            #pragma unroll 4
            for (int j = 0; j < 16; ++j) {
                int k = kk0 + j;
                const float* ar = &sm[OFF_AT + k * LDN + r0];
                u64 a0 = lds2(ar), a1 = lds2(ar + 2), a2 = lds2(ar + 4), a3 = lds2(ar + 6);
                const float* br = &sm[OFF_W + j * LDW + c0];
                float4 bv0 = *(const float4*)br;
                float4 bv1 = *(const float4*)(br + 4);
                float bs[8] = {bv0.x,bv0.y,bv0.z,bv0.w, bv1.x,bv1.y,bv1.z,bv1.w};
                #pragma unroll
                for (int cc = 0; cc < 8; ++cc) {
                    u64 bb = pk2(bs[cc]);
                    acc[0][cc] = f2fma(a0, bb, acc[0][cc]);
                    acc[1][cc] = f2fma(a1, bb, acc[1][cc]);
                    acc[2][cc] = f2fma(a2, bb, acc[2][cc]);
                    acc[3][cc] = f2fma(a3, bb, acc[3][cc]);
                }
            }
        }
        // bias + writeback (disjoint regions from GEMM1 reads -> no extra sync needed)
        float bias[8];
        *(float4*)&bias[0] = *(const float4*)(qkv_b + c0);
        *(float4*)&bias[4] = *(const float4*)(qkv_b + c0 + 4);
        if (c0 < 128) {   // K part -> transposed k_t[c][n], pairs stay packed
            #pragma unroll
            for (int cc = 0; cc < 8; ++cc) {
                u64 bb = pk2(bias[cc]);
                int c = c0 + cc;
                #pragma unroll
                for (int p = 0; p < 4; ++p)
                    *(u64*)&sm[OFF_KT + c * LDN + r0 + 2*p] = f2add(acc[p][cc], bb);
            }
        } else {          // V part -> row-major v[n][c']
            #pragma unroll
            for (int cc = 0; cc < 8; ++cc) {
                int c = c0 + cc - 128;
                #pragma unroll
                for (int p = 0; p < 4; ++p) {
                    float lo, hi; upk2(acc[p][cc], lo, hi);
                    sm[OFF_V + (r0 + 2*p    ) * LDV + c] = lo + bias[cc];
                    sm[OFF_V + (r0 + 2*p + 1) * LDV + c] = hi + bias[cc];
                }
            }
        }
    }
    __syncthreads();

    // ============ GEMM2: attn[n][h*64+m] = sum_d q_t[h*32+d][n]*k_t[h*32+d][m] ============
    // output written transposed: attn_t[h*64+m][n]
    {
        const int tc = tid >> 3, tr = tid & 7;
        const int h = tc >> 3, m0 = (tc & 7) << 3, r0 = tr << 3;
        u64 acc[4][8];
        #pragma unroll
        for (int p = 0; p < 4; ++p)
            #pragma unroll
            for (int cc = 0; cc < 8; ++cc) acc[p][cc] = 0ull;
        #pragma unroll 8
        for (int d = 0; d < 32; ++d) {
            int row = (h << 5) + d;
            const float* ar = &sm[OFF_QT + row * LDN + r0];
            u64 a0 = lds2(ar), a1 = lds2(ar + 2), a2 = lds2(ar + 4), a3 = lds2(ar + 6);
            const float* br = &sm[OFF_KT + row * LDN + m0];
            #pragma unroll
            for (int cc = 0; cc < 8; ++cc) {
                u64 bb = pk2(br[cc]);
                acc[0][cc] = f2fma(a0, bb, acc[0][cc]);
                acc[1][cc] = f2fma(a1, bb, acc[1][cc]);
                acc[2][cc] = f2fma(a2, bb, acc[2][cc]);
                acc[3][cc] = f2fma(a3, bb, acc[3][cc]);
            }
        }
        #pragma unroll
        for (int cc = 0; cc < 8; ++cc) {
            int c2 = (h << 6) + m0 + cc;
            #pragma unroll
            for (int p = 0; p < 4; ++p)
                *(u64*)&sm[OFF_AT + c2 * LDN + r0 + 2*p] = acc[p][cc];
        }
    }
    __syncthreads();

    // ============ Softmax over m, with mask + lambda*P_thermal added ============
    // thread = (h, n); reads P row (global, once) + mask row + attn_t column.
    {
        const int h = tid >> 6, n = tid & 63;
        const float lam = lam_p[0];
        const int w = b & (NWN - 1);
        const float4* Pr = (const float4*)(P + ((size_t)((b * NHD + h) * NT + n)) * NT);
        const float4* Mr = (const float4*)(maskp + ((size_t)(w * NT + n)) * NT);
        const int base = OFF_AT + (h << 6) * LDN + n;
        float v[64];
        #pragma unroll
        for (int m4 = 0; m4 < 16; ++m4) {
            float4 pv = Pr[m4];
            float4 mv = Mr[m4];
            v[4*m4+0] = sm[base + (4*m4+0)*LDN] + mv.x + lam * pv.x;
            v[4*m4+1] = sm[base + (4*m4+1)*LDN] + mv.y + lam * pv.y;
            v[4*m4+2] = sm[base + (4*m4+2)*LDN] + mv.z + lam * pv.z;
            v[4*m4+3] = sm[base + (4*m4+3)*LDN] + mv.w + lam * pv.w;
        }
        float mx = v[0];
        #pragma unroll
        for (int m = 1; m < 64; ++m) mx = fmaxf(mx, v[m]);
        float s = 0.f;
        #pragma unroll
        for (int m = 0; m < 64; ++m) { v[m] = __expf(v[m] - mx); s += v[m]; }
        float inv = 1.0f / s;
        #pragma unroll
        for (int m = 0; m < 64; ++m) sm[base + m * LDN] = v[m] * inv;
    }
    __syncthreads();

    // ============ GEMM3: o[n][j] = sum_m attn_t[h*64+m][n] * v[m][j], h=j/32 ============
    // output written transposed into o_t[j][n] (aliases dead q_t region).
    {
        const int tc = tid >> 3, tr = tid & 7;
        const int j0 = tc << 2, h = tc >> 3, r0 = tr << 3;
        u64 acc[4][4];
        #pragma unroll
        for (int p = 0; p < 4; ++p)
            #pragma unroll
            for (int cc = 0; cc < 4; ++cc) acc[p][cc] = 0ull;
        #pragma unroll 8
        for (int m = 0; m < 64; ++m) {
            const float* ar = &sm[OFF_AT + ((h << 6) + m) * LDN + r0];
            u64 a0 = lds2(ar), a1 = lds2(ar + 2), a2 = lds2(ar + 4), a3 = lds2(ar + 6);
            float4 bv = *(const float4*)&sm[OFF_V + m * LDV + j0];
            float bs[4] = {bv.x, bv.y, bv.z, bv.w};
            #pragma unroll
            for (int cc = 0; cc < 4; ++cc) {
                u64 bb = pk2(bs[cc]);
                acc[0][cc] = f2fma(a0, bb, acc[0][cc]);
                acc[1][cc] = f2fma(a1, bb, acc[1][cc]);
                acc[2][cc] = f2fma(a2, bb, acc[2][cc]);
                acc[3][cc] = f2fma(a3, bb, acc[3][cc]);
            }
        }
        #pragma unroll
        for (int cc = 0; cc < 4; ++cc) {
            int jj = j0 + cc;
            #pragma unroll
            for (int p = 0; p < 4; ++p)
                *(u64*)&sm[OFF_QT + jj * LDN + r0 + 2*p] = acc[p][cc];
        }
    }
    __syncthreads();

    // ============ Stage proj_w transposed: p_t[j][c] (aliases dead attn region) ============
    {
        const int c = tid >> 1, hf = tid & 1;
        const float* pr = proj_w + c * 128 + hf * 64;
        #pragma unroll
        for (int q = 0; q < 16; ++q) {
            float4 pv = ((const float4*)pr)[q];
            int j = hf * 64 + (q << 2);
            sm[OFF_AT + (j    ) * LDP + c] = pv.x;
            sm[OFF_AT + (j + 1) * LDP + c] = pv.y;
            sm[OFF_AT + (j + 2) * LDP + c] = pv.z;
            sm[OFF_AT + (j + 3) * LDP + c] = pv.w;
        }
    }
    __syncthreads();

    // ============ GEMM4: res[n][c] = sum_j o_t[j][n]*p_t[j][c] + proj_b[c] ============
    {
        const int tc = tid >> 3, tr = tid & 7;
        const int c0 = tc << 2, r0 = tr << 3;
        u64 acc[4][4];
        #pragma unroll
        for (int p = 0; p < 4; ++p)
            #pragma unroll
            for (int cc = 0; cc < 4; ++cc) acc[p][cc] = 0ull;
        #pragma unroll 8
        for (int j = 0; j < 128; ++j) {
            const float* ar = &sm[OFF_QT + j * LDN + r0];
            u64 a0 = lds2(ar), a1 = lds2(ar + 2), a2 = lds2(ar + 4), a3 = lds2(ar + 6);
            float4 bv = *(const float4*)&sm[OFF_AT + j * LDP + c0];
            float bs[4] = {bv.x, bv.y, bv.z, bv.w};
            #pragma unroll
            for (int cc = 0; cc < 4; ++cc) {
                u64 bb = pk2(bs[cc]);
                acc[0][cc] = f2fma(a0, bb, acc[0][cc]);
                acc[1][cc] = f2fma(a1, bb, acc[1][cc]);
                acc[2][cc] = f2fma(a2, bb, acc[2][cc]);
                acc[3][cc] = f2fma(a3, bb, acc[3][cc]);
            }
        }
        float4 pb4 = *(const float4*)(proj_b + c0);
        float pbs[4] = {pb4.x, pb4.y, pb4.z, pb4.w};
        float* ob = out + (size_t)b * 8192;
        #pragma unroll
        for (int p = 0; p < 4; ++p) {
            float lo0, hi0, lo1, hi1, lo2, hi2, lo3, hi3;
            upk2(acc[p][0], lo0, hi0); upk2(acc[p][1], lo1, hi1);
            upk2(acc[p][2], lo2, hi2); upk2(acc[p][3], lo3, hi3);
            float4 lo4 = make_float4(lo0 + pbs[0], lo1 + pbs[1], lo2 + pbs[2], lo3 + pbs[3]);
            float4 hi4 = make_float4(hi0 + pbs[0], hi1 + pbs[1], hi2 + pbs[2], hi3 + pbs[3]);
            *(float4*)&ob[(r0 + 2*p    ) * 128 + c0] = lo4;
            *(float4*)&ob[(r0 + 2*p + 1) * 128 + c0] = hi4;
        }
    }
}

extern "C" void kernel_launch(void* const* d_in, const int* in_sizes, int n_in,
                              void* d_out, int out_size)
{
    const float* x      = (const float*)d_in[0];
    const float* y      = (const float*)d_in[1];
    const float* P      = (const float*)d_in[2];
    const float* maskp  = (const float*)d_in[3];
    const float* qkv_w  = (const float*)d_in[4];
    const float* qkv_b  = (const float*)d_in[5];
    const float* proj_w = (const float*)d_in[6];
    const float* proj_b = (const float*)d_in[7];
    const float* lam    = (const float*)d_in[8];
    float* out = (float*)d_out;

    cudaFuncSetAttribute(wattn_kernel,
                         cudaFuncAttributeMaxDynamicSharedMemorySize, SMEM_BYTES);
    wattn_kernel<<<NB, 256, SMEM_BYTES>>>(x, y, P, maskp, qkv_w, qkv_b,
                                          proj_w, proj_b, lam, out);
}